// round 10
// baseline (speedup 1.0000x reference)
#include <cuda_runtime.h>
#include <cuda_fp16.h>
#include <cuda_bf16.h>
#include <math.h>

#define MAX_N 100000
#define MAX_E 1250000
#define IN_DIM 128
#define HID 64
#define OUT 16
#define SCAN_BLK 1024
#define MAX_NB 128

typedef unsigned long long ull;

// Scratch (allocation-free rule: __device__ globals)
__device__ int      g_deg[MAX_N];
__device__ float    g_dis[MAX_N];
__device__ int      g_rowstart[MAX_N + 1];
__device__ int      g_cursor[MAX_N];
__device__ int      g_bsum[MAX_NB];
__device__ int      g_boff[MAX_NB];
__device__ int      g_csrc[MAX_E];
__device__ __half2  g_h[MAX_N * 32];            // x @ W1 (unscaled), fp16
__device__ unsigned g_w1t[HID * (IN_DIM / 2)];  // W1^T bf16x2: [n][k/2]
__device__ int      g_is64;

__device__ __forceinline__ unsigned bf16x2_of(float lo, float hi) {
    unsigned r;
    asm("cvt.rn.bf16x2.f32 %0, %1, %2;" : "=r"(r) : "f"(hi), "f"(lo));
    return r;
}
__device__ __forceinline__ unsigned smem_u32(const void* p) {
    unsigned a;
    asm("{ .reg .u64 t; cvta.to.shared.u64 t, %1; cvt.u32.u64 %0, t; }" : "=r"(a) : "l"(p));
    return a;
}

// ---------------------------------------------------------------
// launch 0: zero deg, dtype probe, build W1^T bf16 scratch
__global__ void k_init_probe(int N, const int* __restrict__ ei32, int n_words,
                             const float* __restrict__ W1) {
    int i = blockIdx.x * blockDim.x + threadIdx.x;
    if (i == 0) g_is64 = 1;
    if (i < N) g_deg[i] = 0;
    if (i < 4096) {
        long long stride = (long long)n_words / 8192;
        if (stride < 1) stride = 1;
        long long w = 1 + 2 * (stride * i);
        if (w < n_words && ei32[w] != 0) g_is64 = 0;
    }
    if (i < HID * (IN_DIM / 2)) {          // 4096 pairs
        int n  = i >> 6;                   // 0..63
        int k  = (i & 63) * 2;             // even k
        g_w1t[i] = bf16x2_of(W1[k * HID + n], W1[(k + 1) * HID + n]);
    }
}
__device__ __forceinline__ int edge_at(const void* ei, long long i, int is64) {
    if (is64) return (int)((const long long*)ei)[i];
    return ((const int*)ei)[i];
}

// launch 1 (side stream): degree count, 4 edges/thread
__global__ void k_deg_count(const void* __restrict__ ei, int E, int N) {
    int base = 4 * (blockIdx.x * blockDim.x + threadIdx.x);
    int is64 = g_is64;
    #pragma unroll
    for (int u = 0; u < 4; u++) {
        int e = base + u;
        if (e < E) {
            int dst = edge_at(ei, (long long)E + e, is64);
            if ((unsigned)dst < (unsigned)N) atomicAdd(&g_deg[dst], 1);
        }
    }
}

// ---------------------------------------------------------------
// launch 2 (side stream): scan1
__global__ void k_scan1(int N) {
    __shared__ int s[256];
    int t = threadIdx.x;
    int base = blockIdx.x * SCAN_BLK + t * 4;
    int v0 = (base + 0 < N) ? g_deg[base + 0] : 0;
    int v1 = (base + 1 < N) ? g_deg[base + 1] : 0;
    int v2 = (base + 2 < N) ? g_deg[base + 2] : 0;
    int v3 = (base + 3 < N) ? g_deg[base + 3] : 0;
    int sum = v0 + v1 + v2 + v3;
    s[t] = sum;
    __syncthreads();
    for (int off = 1; off < 256; off <<= 1) {
        int x = (t >= off) ? s[t - off] : 0;
        __syncthreads();
        s[t] += x;
        __syncthreads();
    }
    int run = s[t] - sum;
    if (base + 0 < N) g_rowstart[base + 0] = run;  run += v0;
    if (base + 1 < N) g_rowstart[base + 1] = run;  run += v1;
    if (base + 2 < N) g_rowstart[base + 2] = run;  run += v2;
    if (base + 3 < N) g_rowstart[base + 3] = run;
    if (t == 255) g_bsum[blockIdx.x] = s[255];
}

// ---------------------------------------------------------------
// launch 3 (main, ncu-captured): gemm1 via mma.sync (bf16 HMMA)
// h = fp16(x @ W1), unscaled. 128 rows/block, 256 threads, K=128 in 8 k-tiles.
__global__ void __launch_bounds__(256) k_gemm1_mma(
        const float* __restrict__ x, int N) {
    __shared__ __align__(16) unsigned char smx[128 * 256];  // 128 rows x 256B bf16

    int tid  = threadIdx.x;
    int w    = tid >> 5;
    int l    = tid & 31;
    int row0 = blockIdx.x * 128;

    // Stage x (fp32 -> bf16), swizzled 16B chunks: chunk c of row r at
    // r*256 + ((c ^ (r&7)) * 16).
    for (int ci = tid; ci < 128 * 16; ci += 256) {
        int r = ci >> 4;
        int c = ci & 15;
        int row = row0 + r;
        uint4 pk;
        if (row < N) {
            const float4* xp = (const float4*)(x + (size_t)row * IN_DIM + c * 8);
            float4 v0 = __ldg(&xp[0]);
            float4 v1 = __ldg(&xp[1]);
            pk.x = bf16x2_of(v0.x, v0.y);
            pk.y = bf16x2_of(v0.z, v0.w);
            pk.z = bf16x2_of(v1.x, v1.y);
            pk.w = bf16x2_of(v1.z, v1.w);
        } else {
            pk = make_uint4(0, 0, 0, 0);
        }
        *(uint4*)&smx[r * 256 + ((c ^ (r & 7)) << 4)] = pk;
    }
    __syncthreads();

    float acc[8][4];
    #pragma unroll
    for (int nt = 0; nt < 8; nt++)
        #pragma unroll
        for (int j = 0; j < 4; j++) acc[nt][j] = 0.0f;

    int g   = l >> 2;
    int tig = l & 3;
    int lrow = w * 16 + (l & 15);
    int kch  = (l >> 4);
    unsigned sb = smem_u32(smx);

    #pragma unroll
    for (int kt = 0; kt < 8; kt++) {
        unsigned a0, a1, a2, a3;
        unsigned addr = sb + lrow * 256 + ((((kt << 1) | kch) ^ (lrow & 7)) << 4);
        asm volatile("ldmatrix.sync.aligned.m8n8.x4.shared.b16 {%0,%1,%2,%3}, [%4];"
                     : "=r"(a0), "=r"(a1), "=r"(a2), "=r"(a3) : "r"(addr));

        #pragma unroll
        for (int nt = 0; nt < 8; nt++) {
            int n = nt * 8 + g;
            unsigned b0 = __ldg(&g_w1t[n * 64 + kt * 8 + tig]);
            unsigned b1 = __ldg(&g_w1t[n * 64 + kt * 8 + tig + 4]);
            asm volatile(
                "mma.sync.aligned.m16n8k16.row.col.f32.bf16.bf16.f32 "
                "{%0,%1,%2,%3}, {%4,%5,%6,%7}, {%8,%9}, {%0,%1,%2,%3};"
                : "+f"(acc[nt][0]), "+f"(acc[nt][1]), "+f"(acc[nt][2]), "+f"(acc[nt][3])
                : "r"(a0), "r"(a1), "r"(a2), "r"(a3), "r"(b0), "r"(b1));
        }
    }

    int rA = row0 + w * 16 + g;
    int rB = rA + 8;
    #pragma unroll
    for (int nt = 0; nt < 8; nt++) {
        int h2i = nt * 4 + tig;
        if (rA < N)
            g_h[(size_t)rA * 32 + h2i] = __floats2half2_rn(acc[nt][0], acc[nt][1]);
        if (rB < N)
            g_h[(size_t)rB * 32 + h2i] = __floats2half2_rn(acc[nt][2], acc[nt][3]);
    }
}

// ---------------------------------------------------------------
__global__ void k_scan2(int NB, int N) {
    __shared__ int s[MAX_NB];
    int t = threadIdx.x;
    int v = (t < NB) ? g_bsum[t] : 0;
    s[t] = v;
    __syncthreads();
    for (int off = 1; off < MAX_NB; off <<= 1) {
        int x = (t >= off) ? s[t - off] : 0;
        __syncthreads();
        s[t] += x;
        __syncthreads();
    }
    g_boff[t] = s[t] - v;
    if (t == MAX_NB - 1) g_rowstart[N] = s[MAX_NB - 1];
}

// scan3: finalize rowstart/cursor; also write dis = rsqrt(deg+1)
__global__ void k_scan3(int N) {
    int i = blockIdx.x * blockDim.x + threadIdx.x;
    if (i < N) {
        int r = g_rowstart[i] + g_boff[i >> 10];
        g_rowstart[i] = r;
        g_cursor[i] = r;
        g_dis[i] = rsqrtf((float)(g_deg[i] + 1));
    }
}

// CSR fill, 2 edges/thread
__global__ void k_fill(const void* __restrict__ ei, int E, int N) {
    int base = 2 * (blockIdx.x * blockDim.x + threadIdx.x);
    int is64 = g_is64;
    #pragma unroll
    for (int u = 0; u < 2; u++) {
        int e = base + u;
        if (e < E) {
            int src = edge_at(ei, e, is64);
            int dst = edge_at(ei, (long long)E + e, is64);
            if ((unsigned)src < (unsigned)N && (unsigned)dst < (unsigned)N) {
                int pos = atomicAdd(&g_cursor[dst], 1);
                if (pos < MAX_E) g_csrc[pos] = src;
            }
        }
    }
}

// ---------------------------------------------------------------
// agg + relu + gemm2 + log_softmax, fused. One warp/node.
// Messages: h[src] * dis[src] (gathered per-lane, shfl-broadcast), final * dn.
__global__ void __launch_bounds__(256) k_agg(
        const float* __restrict__ b1,
        const float* __restrict__ W2,
        const float* __restrict__ b2,
        float* __restrict__ out, int N) {
    __shared__ float sW2[HID * OUT];
    __shared__ float sb1[HID];
    __shared__ float sb2[OUT];
    __shared__ float sv[8][HID];

    int tid = threadIdx.x;
    for (int i = tid; i < HID * OUT; i += 256) sW2[i] = W2[i];
    if (tid < HID) sb1[tid] = b1[tid];
    if (tid < OUT) sb2[tid] = b2[tid];
    __syncthreads();

    int wid  = tid >> 5;
    int lane = tid & 31;
    int node = blockIdx.x * 8 + wid;
    if (node >= N) return;

    float dn = g_dis[node];

    // self-loop: weight dis[node]
    float2 acc;
    {
        float2 f = __half22float2(g_h[(size_t)node * 32 + lane]);
        acc.x = f.x * dn;
        acc.y = f.y * dn;
    }

    int beg = g_rowstart[node];
    int end = g_rowstart[node + 1];

    for (int j0 = beg; j0 < end; j0 += 32) {
        int cnt = end - j0;
        if (cnt > 32) cnt = 32;
        int myidx = 0;
        float myd = 0.0f;
        if (lane < cnt) {
            myidx = __ldg(&g_csrc[j0 + lane]);
            myd   = __ldg(&g_dis[myidx]);
        }

        int k = 0;
        for (; k + 4 <= cnt; k += 4) {
            int s0 = __shfl_sync(0xffffffffu, myidx, k);
            int s1 = __shfl_sync(0xffffffffu, myidx, k + 1);
            int s2 = __shfl_sync(0xffffffffu, myidx, k + 2);
            int s3 = __shfl_sync(0xffffffffu, myidx, k + 3);
            float w0 = __shfl_sync(0xffffffffu, myd, k);
            float w1 = __shfl_sync(0xffffffffu, myd, k + 1);
            float w2 = __shfl_sync(0xffffffffu, myd, k + 2);
            float w3 = __shfl_sync(0xffffffffu, myd, k + 3);
            float2 f0 = __half22float2(g_h[(size_t)s0 * 32 + lane]);
            float2 f1 = __half22float2(g_h[(size_t)s1 * 32 + lane]);
            float2 f2 = __half22float2(g_h[(size_t)s2 * 32 + lane]);
            float2 f3 = __half22float2(g_h[(size_t)s3 * 32 + lane]);
            acc.x = fmaf(f0.x, w0, acc.x); acc.y = fmaf(f0.y, w0, acc.y);
            acc.x = fmaf(f1.x, w1, acc.x); acc.y = fmaf(f1.y, w1, acc.y);
            acc.x = fmaf(f2.x, w2, acc.x); acc.y = fmaf(f2.y, w2, acc.y);
            acc.x = fmaf(f3.x, w3, acc.x); acc.y = fmaf(f3.y, w3, acc.y);
        }
        for (; k < cnt; k++) {
            int s0 = __shfl_sync(0xffffffffu, myidx, k);
            float w0 = __shfl_sync(0xffffffffu, myd, k);
            float2 f0 = __half22float2(g_h[(size_t)s0 * 32 + lane]);
            acc.x = fmaf(f0.x, w0, acc.x);
            acc.y = fmaf(f0.y, w0, acc.y);
        }
    }

    sv[wid][2 * lane]     = fmaxf(fmaf(acc.x, dn, sb1[2 * lane]), 0.0f);
    sv[wid][2 * lane + 1] = fmaxf(fmaf(acc.y, dn, sb1[2 * lane + 1]), 0.0f);
    __syncwarp();

    if (lane < OUT) {
        int c = lane;
        float sum = sb2[c];
        #pragma unroll 8
        for (int k = 0; k < HID; k++)
            sum = fmaf(sv[wid][k], sW2[k * OUT + c], sum);

        float m = sum;
        #pragma unroll
        for (int off = 8; off >= 1; off >>= 1)
            m = fmaxf(m, __shfl_xor_sync(0x0000ffffu, m, off));
        float ex = __expf(sum - m);
        float tot = ex;
        #pragma unroll
        for (int off = 8; off >= 1; off >>= 1)
            tot += __shfl_xor_sync(0x0000ffffu, tot, off);
        out[(size_t)node * OUT + c] = sum - m - __logf(tot);
    }
}

// ---------------------------------------------------------------
static cudaStream_t g_s2;
static cudaEvent_t  g_evFork, g_evJoin;
static struct HxInit {
    HxInit() {
        cudaStreamCreateWithFlags(&g_s2, cudaStreamNonBlocking);
        cudaEventCreateWithFlags(&g_evFork, cudaEventDisableTiming);
        cudaEventCreateWithFlags(&g_evJoin, cudaEventDisableTiming);
    }
} g_hx_init;

extern "C" void kernel_launch(void* const* d_in, const int* in_sizes, int n_in,
                              void* d_out, int out_size) {
    const float* x   = (const float*)d_in[0];
    const void*  ei  = d_in[1];
    const float* W1  = (const float*)d_in[2];
    const float* b1  = (const float*)d_in[3];
    const float* W2  = (const float*)d_in[4];
    const float* b2  = (const float*)d_in[5];
    float* out = (float*)d_out;

    int N = in_sizes[0] / IN_DIM;     // 100000
    int E = in_sizes[1] / 2;          // 1250000
    int NB = (N + SCAN_BLK - 1) / SCAN_BLK;

    // launch 0: init (both branches depend on it)
    k_init_probe<<<(N + 255) / 256, 256>>>(N, (const int*)ei, in_sizes[1], W1);

    cudaEventRecord(g_evFork, 0);
    cudaStreamWaitEvent(g_s2, g_evFork, 0);

    // side stream: full CSR chain (gemm1 no longer depends on deg)
    k_deg_count<<<(E + 1023) / 1024, 256, 0, g_s2>>>(ei, E, N);   // 1
    k_scan1<<<NB, 256, 0, g_s2>>>(N);                             // 2

    // main stream: gemm1 (launch 3 -> ncu)
    k_gemm1_mma<<<(N + 127) / 128, 256>>>(x, N);                  // 3 <- ncu

    k_scan2<<<1, MAX_NB, 0, g_s2>>>(NB, N);                       // 4
    k_scan3<<<(N + 255) / 256, 256, 0, g_s2>>>(N);                // 5
    k_fill<<<(E + 511) / 512, 256, 0, g_s2>>>(ei, E, N);          // 6

    cudaEventRecord(g_evJoin, g_s2);
    cudaStreamWaitEvent(0, g_evJoin, 0);

    k_agg<<<(N + 7) / 8, 256>>>(b1, W2, b2, out, N);              // 7
}

// round 11
// speedup vs baseline: 1.1840x; 1.1840x over previous
#include <cuda_runtime.h>
#include <cuda_fp16.h>
#include <cuda_bf16.h>
#include <math.h>

#define MAX_N 100000
#define MAX_E 1250000
#define IN_DIM 128
#define HID 64
#define OUT 16
#define SCAN_BLK 1024
#define MAX_NB 128

typedef unsigned long long ull;

// Scratch (allocation-free rule: __device__ globals)
__device__ int      g_deg[MAX_N];
__device__ float    g_dis[MAX_N];
__device__ int      g_rowstart[MAX_N + 1];
__device__ int      g_cursor[MAX_N];
__device__ int      g_bsum[MAX_NB];
__device__ uint2    g_edge[MAX_E];              // {src, dis[src] bits}, dst-grouped
__device__ __half2  g_h[MAX_N * 32];            // x @ W1 (unscaled), fp16
__device__ unsigned g_w1t[HID * (IN_DIM / 2)];  // W1^T bf16x2: [n][k/2]
__device__ int      g_is64;

__device__ __forceinline__ unsigned bf16x2_of(float lo, float hi) {
    unsigned r;
    asm("cvt.rn.bf16x2.f32 %0, %1, %2;" : "=r"(r) : "f"(hi), "f"(lo));
    return r;
}
__device__ __forceinline__ unsigned smem_u32(const void* p) {
    unsigned a;
    asm("{ .reg .u64 t; cvta.to.shared.u64 t, %1; cvt.u32.u64 %0, t; }" : "=r"(a) : "l"(p));
    return a;
}

// ---------------------------------------------------------------
// launch 0: zero deg, dtype probe, build W1^T bf16 scratch
__global__ void k_init_probe(int N, const int* __restrict__ ei32, int n_words,
                             const float* __restrict__ W1) {
    int i = blockIdx.x * blockDim.x + threadIdx.x;
    if (i == 0) g_is64 = 1;
    if (i < N) g_deg[i] = 0;
    if (i < 4096) {
        long long stride = (long long)n_words / 8192;
        if (stride < 1) stride = 1;
        long long w = 1 + 2 * (stride * i);
        if (w < n_words && ei32[w] != 0) g_is64 = 0;
    }
    if (i < HID * (IN_DIM / 2)) {          // 4096 pairs
        int n  = i >> 6;
        int k  = (i & 63) * 2;
        g_w1t[i] = bf16x2_of(W1[k * HID + n], W1[(k + 1) * HID + n]);
    }
}
__device__ __forceinline__ int edge_at(const void* ei, long long i, int is64) {
    if (is64) return (int)((const long long*)ei)[i];
    return ((const int*)ei)[i];
}

// launch 1 (side): degree count, 4 edges/thread
__global__ void k_deg_count(const void* __restrict__ ei, int E, int N) {
    int base = 4 * (blockIdx.x * blockDim.x + threadIdx.x);
    int is64 = g_is64;
    #pragma unroll
    for (int u = 0; u < 4; u++) {
        int e = base + u;
        if (e < E) {
            int dst = edge_at(ei, (long long)E + e, is64);
            if ((unsigned)dst < (unsigned)N) atomicAdd(&g_deg[dst], 1);
        }
    }
}

// launch 2 (side): per-block exclusive scan
__global__ void k_scan1(int N) {
    __shared__ int s[256];
    int t = threadIdx.x;
    int base = blockIdx.x * SCAN_BLK + t * 4;
    int v0 = (base + 0 < N) ? g_deg[base + 0] : 0;
    int v1 = (base + 1 < N) ? g_deg[base + 1] : 0;
    int v2 = (base + 2 < N) ? g_deg[base + 2] : 0;
    int v3 = (base + 3 < N) ? g_deg[base + 3] : 0;
    int sum = v0 + v1 + v2 + v3;
    s[t] = sum;
    __syncthreads();
    for (int off = 1; off < 256; off <<= 1) {
        int x = (t >= off) ? s[t - off] : 0;
        __syncthreads();
        s[t] += x;
        __syncthreads();
    }
    int run = s[t] - sum;
    if (base + 0 < N) g_rowstart[base + 0] = run;  run += v0;
    if (base + 1 < N) g_rowstart[base + 1] = run;  run += v1;
    if (base + 2 < N) g_rowstart[base + 2] = run;  run += v2;
    if (base + 3 < N) g_rowstart[base + 3] = run;
    if (t == 255) g_bsum[blockIdx.x] = s[255];
}

// ---------------------------------------------------------------
// launch 3 (main, ncu): gemm1 via mma.sync bf16; A and B both via ldmatrix.
// 64 rows/block, 128 threads (4 warps x 16 rows x 64 cols). K=128, 8 k-tiles.
__global__ void __launch_bounds__(128) k_gemm1_mma(
        const float* __restrict__ x, int N) {
    // [0,16K): A tile 64 rows x 256B (bf16, swizzled 16B chunks)
    // [16K,32K): B = W1^T 64 rows(n) x 256B (bf16, swizzled 16B chunks)
    __shared__ __align__(16) unsigned char sm[32768];

    int tid  = threadIdx.x;
    int w    = tid >> 5;
    int l    = tid & 31;
    int row0 = blockIdx.x * 64;

    // Stage A: x fp32 -> bf16; chunk c of row r at r*256 + ((c^(r&7))<<4)
    for (int ci = tid; ci < 64 * 16; ci += 128) {
        int r = ci >> 4;
        int c = ci & 15;
        int row = row0 + r;
        uint4 pk;
        if (row < N) {
            const float4* xp = (const float4*)(x + (size_t)row * IN_DIM + c * 8);
            float4 v0 = __ldg(&xp[0]);
            float4 v1 = __ldg(&xp[1]);
            pk.x = bf16x2_of(v0.x, v0.y);
            pk.y = bf16x2_of(v0.z, v0.w);
            pk.z = bf16x2_of(v1.x, v1.y);
            pk.w = bf16x2_of(v1.z, v1.w);
        } else {
            pk = make_uint4(0, 0, 0, 0);
        }
        *(uint4*)&sm[r * 256 + ((c ^ (r & 7)) << 4)] = pk;
    }
    // Stage B: g_w1t word i -> row n=i>>6, kpair kp=i&63, chunk c=kp>>2, word kp&3
    for (int i = tid; i < 4096; i += 128) {
        int n  = i >> 6;
        int kp = i & 63;
        int c  = kp >> 2;
        *(unsigned*)&sm[16384 + n * 256 + (((c) ^ (n & 7)) << 4) + (kp & 3) * 4] =
            __ldg(&g_w1t[i]);
    }
    __syncthreads();

    float acc[8][4];
    #pragma unroll
    for (int nt = 0; nt < 8; nt++)
        #pragma unroll
        for (int j = 0; j < 4; j++) acc[nt][j] = 0.0f;

    unsigned sb = smem_u32(sm);
    // A ldmatrix lane addr: rows w*16 + (l&15), chunk kt*2 + (l>>4)
    int arow = w * 16 + (l & 15);
    int akch = l >> 4;
    // B ldmatrix lane addr (per pair p): quad = l>>3: n = p*16 + (quad>>1)*8 + (l&7),
    // chunk = kt*2 + (quad&1)
    int bq   = l >> 3;
    int br   = (l & 7) + ((bq >> 1) << 3);   // row within 16-row group
    int bkch = bq & 1;

    #pragma unroll
    for (int kt = 0; kt < 8; kt++) {
        unsigned a0, a1, a2, a3;
        {
            unsigned addr = sb + arow * 256 + ((((kt << 1) | akch) ^ (arow & 7)) << 4);
            asm volatile("ldmatrix.sync.aligned.m8n8.x4.shared.b16 {%0,%1,%2,%3}, [%4];"
                         : "=r"(a0), "=r"(a1), "=r"(a2), "=r"(a3) : "r"(addr));
        }
        #pragma unroll
        for (int p = 0; p < 4; p++) {
            int n = p * 16 + br;
            unsigned addr = sb + 16384 + n * 256 +
                            ((((kt << 1) | bkch) ^ (n & 7)) << 4);
            unsigned b0, b1, b2, b3;
            asm volatile("ldmatrix.sync.aligned.m8n8.x4.shared.b16 {%0,%1,%2,%3}, [%4];"
                         : "=r"(b0), "=r"(b1), "=r"(b2), "=r"(b3) : "r"(addr));
            asm volatile(
                "mma.sync.aligned.m16n8k16.row.col.f32.bf16.bf16.f32 "
                "{%0,%1,%2,%3}, {%4,%5,%6,%7}, {%8,%9}, {%0,%1,%2,%3};"
                : "+f"(acc[2*p][0]), "+f"(acc[2*p][1]), "+f"(acc[2*p][2]), "+f"(acc[2*p][3])
                : "r"(a0), "r"(a1), "r"(a2), "r"(a3), "r"(b0), "r"(b1));
            asm volatile(
                "mma.sync.aligned.m16n8k16.row.col.f32.bf16.bf16.f32 "
                "{%0,%1,%2,%3}, {%4,%5,%6,%7}, {%8,%9}, {%0,%1,%2,%3};"
                : "+f"(acc[2*p+1][0]), "+f"(acc[2*p+1][1]), "+f"(acc[2*p+1][2]), "+f"(acc[2*p+1][3])
                : "r"(a0), "r"(a1), "r"(a2), "r"(a3), "r"(b2), "r"(b3));
        }
    }

    int g   = l >> 2;
    int tig = l & 3;
    int rA = row0 + w * 16 + g;
    int rB = rA + 8;
    #pragma unroll
    for (int nt = 0; nt < 8; nt++) {
        int h2i = nt * 4 + tig;
        if (rA < N)
            g_h[(size_t)rA * 32 + h2i] = __floats2half2_rn(acc[nt][0], acc[nt][1]);
        if (rB < N)
            g_h[(size_t)rB * 32 + h2i] = __floats2half2_rn(acc[nt][2], acc[nt][3]);
    }
}

// ---------------------------------------------------------------
// launch 4 (side): finish scan (each block locally scans the 98 block sums),
// write rowstart/cursor/dis.
__global__ void k_scanB(int NB, int N) {
    __shared__ int boff;
    int i = blockIdx.x * blockDim.x + threadIdx.x;
    if (threadIdx.x == 0) {
        int myblk = (blockIdx.x * blockDim.x) >> 10;   // scan1 block of this range
        int s = 0;
        for (int b = 0; b < myblk; b++) s += g_bsum[b];
        boff = s;
    }
    __syncthreads();
    if (i < N) {
        int r = g_rowstart[i] + boff;
        g_rowstart[i] = r;
        g_cursor[i] = r;
        g_dis[i] = rsqrtf((float)(g_deg[i] + 1));
        if (i == N - 1) g_rowstart[N] = r + g_deg[i];
    }
}

// launch 5 (side): CSR fill with combined {src, dis[src]} records
__global__ void k_fill(const void* __restrict__ ei, int E, int N) {
    int base = 2 * (blockIdx.x * blockDim.x + threadIdx.x);
    int is64 = g_is64;
    #pragma unroll
    for (int u = 0; u < 2; u++) {
        int e = base + u;
        if (e < E) {
            int src = edge_at(ei, e, is64);
            int dst = edge_at(ei, (long long)E + e, is64);
            if ((unsigned)src < (unsigned)N && (unsigned)dst < (unsigned)N) {
                int pos = atomicAdd(&g_cursor[dst], 1);
                if (pos < MAX_E)
                    g_edge[pos] = make_uint2((unsigned)src,
                                             __float_as_uint(g_dis[src]));
            }
        }
    }
}

// ---------------------------------------------------------------
// launch 6: agg + relu + gemm2 + log_softmax. One warp/node.
// Edge records batch-loaded to smem; inner loop = LDS.64 broadcast + LDG + FMA.
__global__ void __launch_bounds__(256) k_agg(
        const float* __restrict__ b1,
        const float* __restrict__ W2,
        const float* __restrict__ b2,
        float* __restrict__ out, int N) {
    __shared__ float sW2[HID * OUT];
    __shared__ float sb1[HID];
    __shared__ float sb2[OUT];
    __shared__ float sv[8][HID];
    __shared__ uint2 sbat[8][32];

    int tid = threadIdx.x;
    for (int i = tid; i < HID * OUT; i += 256) sW2[i] = W2[i];
    if (tid < HID) sb1[tid] = b1[tid];
    if (tid < OUT) sb2[tid] = b2[tid];
    __syncthreads();

    int wid  = tid >> 5;
    int lane = tid & 31;
    int node = blockIdx.x * 8 + wid;
    if (node >= N) return;

    float dn = g_dis[node];

    // self-loop: h[node] * dn (then whole acc * dn at the end -> dn^2)
    float2 acc;
    {
        float2 f = __half22float2(g_h[(size_t)node * 32 + lane]);
        acc.x = f.x * dn;
        acc.y = f.y * dn;
    }

    int beg = g_rowstart[node];
    int end = g_rowstart[node + 1];

    for (int j0 = beg; j0 < end; j0 += 32) {
        int cnt = end - j0;
        if (cnt > 32) cnt = 32;
        if (lane < cnt) sbat[wid][lane] = __ldg(&g_edge[j0 + lane]);
        __syncwarp();

        int k = 0;
        for (; k + 4 <= cnt; k += 4) {
            uint2 e0 = sbat[wid][k];
            uint2 e1 = sbat[wid][k + 1];
            uint2 e2 = sbat[wid][k + 2];
            uint2 e3 = sbat[wid][k + 3];
            float2 f0 = __half22float2(g_h[(size_t)e0.x * 32 + lane]);
            float2 f1 = __half22float2(g_h[(size_t)e1.x * 32 + lane]);
            float2 f2 = __half22float2(g_h[(size_t)e2.x * 32 + lane]);
            float2 f3 = __half22float2(g_h[(size_t)e3.x * 32 + lane]);
            float w0 = __uint_as_float(e0.y);
            float w1 = __uint_as_float(e1.y);
            float w2 = __uint_as_float(e2.y);
            float w3 = __uint_as_float(e3.y);
            acc.x = fmaf(f0.x, w0, acc.x); acc.y = fmaf(f0.y, w0, acc.y);
            acc.x = fmaf(f1.x, w1, acc.x); acc.y = fmaf(f1.y, w1, acc.y);
            acc.x = fmaf(f2.x, w2, acc.x); acc.y = fmaf(f2.y, w2, acc.y);
            acc.x = fmaf(f3.x, w3, acc.x); acc.y = fmaf(f3.y, w3, acc.y);
        }
        for (; k < cnt; k++) {
            uint2 e0 = sbat[wid][k];
            float2 f0 = __half22float2(g_h[(size_t)e0.x * 32 + lane]);
            float w0 = __uint_as_float(e0.y);
            acc.x = fmaf(f0.x, w0, acc.x);
            acc.y = fmaf(f0.y, w0, acc.y);
        }
        __syncwarp();
    }

    sv[wid][2 * lane]     = fmaxf(fmaf(acc.x, dn, sb1[2 * lane]), 0.0f);
    sv[wid][2 * lane + 1] = fmaxf(fmaf(acc.y, dn, sb1[2 * lane + 1]), 0.0f);
    __syncwarp();

    if (lane < OUT) {
        int c = lane;
        float sum = sb2[c];
        #pragma unroll 8
        for (int k = 0; k < HID; k++)
            sum = fmaf(sv[wid][k], sW2[k * OUT + c], sum);

        float m = sum;
        #pragma unroll
        for (int off = 8; off >= 1; off >>= 1)
            m = fmaxf(m, __shfl_xor_sync(0x0000ffffu, m, off));
        float ex = __expf(sum - m);
        float tot = ex;
        #pragma unroll
        for (int off = 8; off >= 1; off >>= 1)
            tot += __shfl_xor_sync(0x0000ffffu, tot, off);
        out[(size_t)node * OUT + c] = sum - m - __logf(tot);
    }
}

// ---------------------------------------------------------------
static cudaStream_t g_s2;
static cudaEvent_t  g_evFork, g_evJoin;
static struct HxInit {
    HxInit() {
        cudaStreamCreateWithFlags(&g_s2, cudaStreamNonBlocking);
        cudaEventCreateWithFlags(&g_evFork, cudaEventDisableTiming);
        cudaEventCreateWithFlags(&g_evJoin, cudaEventDisableTiming);
    }
} g_hx_init;

extern "C" void kernel_launch(void* const* d_in, const int* in_sizes, int n_in,
                              void* d_out, int out_size) {
    const float* x   = (const float*)d_in[0];
    const void*  ei  = d_in[1];
    const float* W1  = (const float*)d_in[2];
    const float* b1  = (const float*)d_in[3];
    const float* W2  = (const float*)d_in[4];
    const float* b2  = (const float*)d_in[5];
    float* out = (float*)d_out;

    int N = in_sizes[0] / IN_DIM;     // 100000
    int E = in_sizes[1] / 2;          // 1250000
    int NB = (N + SCAN_BLK - 1) / SCAN_BLK;

    k_init_probe<<<(N + 255) / 256, 256>>>(N, (const int*)ei, in_sizes[1], W1); // 0

    cudaEventRecord(g_evFork, 0);
    cudaStreamWaitEvent(g_s2, g_evFork, 0);

    k_deg_count<<<(E + 1023) / 1024, 256, 0, g_s2>>>(ei, E, N);   // 1
    k_scan1<<<NB, 256, 0, g_s2>>>(N);                             // 2
    k_gemm1_mma<<<(N + 63) / 64, 128>>>(x, N);                    // 3 <- ncu
    k_scanB<<<(N + 255) / 256, 256, 0, g_s2>>>(NB, N);            // 4
    k_fill<<<(E + 511) / 512, 256, 0, g_s2>>>(ei, E, N);          // 5

    cudaEventRecord(g_evJoin, g_s2);
    cudaStreamWaitEvent(0, g_evJoin, 0);

    k_agg<<<(N + 7) / 8, 256>>>(b1, W2, b2, out, N);              // 6
}